// round 12
// baseline (speedup 1.0000x reference)
#include <cuda_runtime.h>

#define CIN  128
#define PP   784          // 28*28
#define NPIX 3136         // 4*784
#define PIMG 900          // 30*30 padded image
#define PADN 3600         // 4*900 per channel
#define NP32 3584         // 4*28*32 padded-32 q-layout per channel
typedef unsigned long long ull;

// ---------------- scratch (device globals; no allocation) ----------------
__device__ __align__(16) float g_y1 [CIN * NPIX];     // conv1x1 out, [c][q]
__device__ __align__(16) float g_zp [CIN * PADN];     // z (bn1+relu), zero-padded 30x30
__device__ __align__(16) float g_p3 [6][CIN * NP32];  // conv3x3 partials, padded-32
__device__ __align__(16) float g_y3p[CIN * PADN];     // conv3x3 combined, zero-padded
__device__ __align__(16) float g_p4 [6][CIN * NP32];  // adder3x3 partials, padded-32
// transposed weights: [ci][co]
__device__ __align__(16) float g_w1t [CIN * CIN];
__device__ __align__(16) float g_wa1t[CIN * CIN];
__device__ __align__(16) float g_w2t [9][CIN * CIN];
__device__ __align__(16) float g_wa2t[9][CIN * CIN];
// BN1 folded params
__device__ float g_sc1[CIN], g_sh1[CIN];

// ---------------- packed f32x2 helpers -----------------------------------
__device__ __forceinline__ ull fma2(ull a, ull b, ull c) {
    ull d; asm("fma.rn.f32x2 %0, %1, %2, %3;" : "=l"(d) : "l"(a), "l"(b), "l"(c)); return d;
}
__device__ __forceinline__ ull add2(ull a, ull b) {
    ull d; asm("add.rn.f32x2 %0, %1, %2;" : "=l"(d) : "l"(a), "l"(b)); return d;
}
__device__ __forceinline__ ull dup2(float w) {
    ull d; asm("mov.b64 %0, {%1, %1};" : "=l"(d) : "f"(w)); return d;
}
__device__ __forceinline__ ull pairmid(ull a, ull b) {   // {hi(a), lo(b)}
    unsigned ha = (unsigned)(a >> 32), lb = (unsigned)b;
    ull d; asm("mov.b64 %0, {%1, %2};" : "=l"(d) : "r"(ha), "r"(lb));
    return d;
}
__device__ __forceinline__ float lo32(ull v) { return __uint_as_float((unsigned)(v & 0xFFFFFFFFu)); }
__device__ __forceinline__ float hi32(ull v) { return __uint_as_float((unsigned)(v >> 32)); }
#define NEG1X2 0xBF800000BF800000ULL
#define ABSM   0x7FFFFFFF7FFFFFFFULL

// =========================================================================
// kprep: transpose weights; fold BN1.
// =========================================================================
__global__ __launch_bounds__(256) void kprep(const float* __restrict__ w1,
                                             const float* __restrict__ wa1,
                                             const float* __restrict__ w2,
                                             const float* __restrict__ wa2,
                                             const float* __restrict__ g1,
                                             const float* __restrict__ b1,
                                             const float* __restrict__ m1,
                                             const float* __restrict__ v1) {
    int i = blockIdx.x * 256 + threadIdx.x;     // 64 blocks -> 16384
    int ci = i >> 7, co = i & 127;
    g_w1t [ci * CIN + co] = w1 [co * CIN + ci];
    g_wa1t[ci * CIN + co] = wa1[co * CIN + ci];
#pragma unroll
    for (int t = 0; t < 9; t++) {
        g_w2t [t][ci * CIN + co] = w2 [(co * CIN + ci) * 9 + t];
        g_wa2t[t][ci * CIN + co] = wa2[(co * CIN + ci) * 9 + t];
    }
    if (blockIdx.x == 0 && threadIdx.x < CIN) {
        int c = threadIdx.x;
        float sc = g1[c] / sqrtf(v1[c] + 1e-5f);
        g_sc1[c] = sc;
        g_sh1[c] = b1[c] - m1[c] * sc;
    }
}

// =========================================================================
// k1/k2: 1x1 conv / adder, FULL ci. CTA 128co x 32px, 256 thr, tile 4co x 4px.
// grid (98). ADDER=true fuses BN1+ReLU, writes padded g_zp. (R11 winner)
// =========================================================================
template <bool ADDER>
__global__ __launch_bounds__(256) void k1x1(const float* __restrict__ x) {
    __shared__ __align__(16) float sA[2][16][32];
    __shared__ __align__(16) float sW[2][16][128];
    __shared__ int sT[32];

    const int tid = threadIdx.x;
    const int col = tid & 7, row = tid >> 3;
    const int qBase = blockIdx.x * 32;

    if (tid < 32) {
        int q = qBase + tid;
        int n = q / PP, p = q - n * PP;
        if (ADDER) {
            int h = p / 28, w = p - h * 28;
            sT[tid] = n * PIMG + (h + 1) * 30 + w + 1;
        } else {
            sT[tid] = n * CIN * PP + p;
        }
    }
    __syncthreads();

    ull acc[4][2];
#pragma unroll
    for (int i = 0; i < 4; i++) { acc[i][0] = 0; acc[i][1] = 0; }

    const float* __restrict__ wsrc = ADDER ? g_wa1t : g_w1t;

    float aReg[2];
    float4 wReg[2];
    auto ldg = [&](int s) {
        int ci0 = s << 4;
#pragma unroll
        for (int k = 0; k < 2; k++) {
            int e = k * 256 + tid;
            int ci = ci0 + (e >> 5), j = e & 31;
            if (ADDER) aReg[k] = g_y1[ci * NPIX + qBase + j];
            else       aReg[k] = x[sT[j] + ci * PP];
        }
#pragma unroll
        for (int k = 0; k < 2; k++) {
            int e4 = (k * 256 + tid) * 4;
            wReg[k] = *(const float4*)&wsrc[(ci0 + (e4 >> 7)) * CIN + (e4 & 127)];
        }
    };
    auto sts = [&](int b) {
#pragma unroll
        for (int k = 0; k < 2; k++) { int e = k * 256 + tid; sA[b][e >> 5][e & 31] = aReg[k]; }
#pragma unroll
        for (int k = 0; k < 2; k++) { int e4 = (k * 256 + tid) * 4; *(float4*)&sW[b][e4 >> 7][e4 & 127] = wReg[k]; }
    };

    ldg(0); sts(0); __syncthreads();
    for (int s = 0; s < 8; s++) {
        int b = s & 1;
        if (s < 7) ldg(s + 1);
#pragma unroll
        for (int ci = 0; ci < 16; ci++) {
            ulonglong2 a01 = *(const ulonglong2*)&sA[b][ci][col * 4];
            float4 w4 = *(const float4*)&sW[b][ci][row * 4];
            float wf[4] = {w4.x, w4.y, w4.z, w4.w};
#pragma unroll
            for (int i = 0; i < 4; i++) {
                ull wd = dup2(wf[i]);
                if (ADDER) {
                    acc[i][0] = add2(acc[i][0], fma2(wd, NEG1X2, a01.x) & ABSM);
                    acc[i][1] = add2(acc[i][1], fma2(wd, NEG1X2, a01.y) & ABSM);
                } else {
                    acc[i][0] = fma2(wd, a01.x, acc[i][0]);
                    acc[i][1] = fma2(wd, a01.y, acc[i][1]);
                }
            }
        }
        if (s < 7) sts(b ^ 1);
        __syncthreads();
    }
    if (ADDER) {
#pragma unroll
        for (int i = 0; i < 4; i++) {
            int co = row * 4 + i;
            float sc = g_sc1[co], sh = g_sh1[co];
            float r0 = fmaxf(fmaf(-lo32(acc[i][0]), sc, sh), 0.f);
            float r1 = fmaxf(fmaf(-hi32(acc[i][0]), sc, sh), 0.f);
            float r2 = fmaxf(fmaf(-lo32(acc[i][1]), sc, sh), 0.f);
            float r3 = fmaxf(fmaf(-hi32(acc[i][1]), sc, sh), 0.f);
            float* zc = &g_zp[co * PADN];
            zc[sT[col * 4]]     = r0;
            zc[sT[col * 4 + 1]] = r1;
            zc[sT[col * 4 + 2]] = r2;
            zc[sT[col * 4 + 3]] = r3;
        }
    } else {
        const int q = qBase + col * 4;
#pragma unroll
        for (int i = 0; i < 4; i++) {
            int co = row * 4 + i;
            *(ull*)&g_y1[co * NPIX + q]     = acc[i][0];
            *(ull*)&g_y1[co * NPIX + q + 2] = acc[i][1];
        }
    }
}

// =========================================================================
// k3/k4: 3x3 conv / adder, kw-FUSED. CTA 128co x 2 image rows (64 padded px),
// 128 thr, tile 8co x 8px. grid (56, 6): x = row-pair, y = kh*2 + ciHalf.
// A staged ONCE per ci-chunk (2 padded input rows of 30), reused by 3 kw taps
// (kw=0/2 even-aligned pairs, kw=1 register repack). Outputs padded-32 layout
// (w 28..31 dead lanes). 8 stages of 8 ci, double-buffered.
// =========================================================================
template <bool ADDER>
__global__ __launch_bounds__(128) void k3x3() {
    __shared__ __align__(16) float sA[2][8][68];      // [ci][rowsel*32 + i]
    __shared__ __align__(16) float sW[2][24][128];    // [ci*3+kw][co]
    __shared__ int sWoff[24];
    __shared__ int sRow[2];

    const int tid = threadIdx.x;
    const int col = tid & 7, row = tid >> 3;
    const int rp = blockIdx.x;                 // row pair (0..55)
    const int kh = blockIdx.y >> 1;
    const int ciBase = (blockIdx.y & 1) * 64;

    if (tid < 24) {
        sWoff[tid] = (kh * 3 + tid % 3) * (CIN * CIN) + (tid / 3) * CIN;
    }
    if (tid < 2) {
        int rr = rp * 2 + tid;
        int n = rr / 28, h = rr - n * 28;
        sRow[tid] = n * PIMG + (h + kh) * 30;
    }
    __syncthreads();
    const int row0 = sRow[0], row1 = sRow[1];

    ull acc[8][4];
#pragma unroll
    for (int i = 0; i < 8; i++)
#pragma unroll
        for (int j = 0; j < 4; j++) acc[i][j] = 0;

    const float* __restrict__ in   = ADDER ? g_y3p : g_zp;
    const float* __restrict__ wsrc = ADDER ? &g_wa2t[0][0] : &g_w2t[0][0];

    float aReg[4];
    float4 wReg[6];
    auto ldg = [&](int st) {
        int cB = ciBase + st * 8;
#pragma unroll
        for (int k = 0; k < 4; k++) {               // A: 8ci x (2 rows x 32)
            int e = k * 128 + tid;
            int ci = e >> 6, j = e & 63;
            int i = j & 31;
            int rb = (j >> 5) ? row1 : row0;
            aReg[k] = (i < 30) ? in[(cB + ci) * PADN + rb + i] : 0.f;
        }
        int wbase = cB * CIN;
#pragma unroll
        for (int k = 0; k < 6; k++) {               // W: 8ci x 3kw x 128co
            int idx = k * 128 + tid;                // 0..767
            int s = idx >> 5;                       // 0..23 = ci*3+kw
            int co = (idx & 31) * 4;
            wReg[k] = *(const float4*)&wsrc[sWoff[s] + wbase + co];
        }
    };
    auto sts = [&](int b) {
#pragma unroll
        for (int k = 0; k < 4; k++) { int e = k * 128 + tid; sA[b][e >> 6][e & 63] = aReg[k]; }
#pragma unroll
        for (int k = 0; k < 6; k++) {
            int idx = k * 128 + tid;
            *(float4*)&sW[b][idx >> 5][(idx & 31) * 4] = wReg[k];
        }
    };

    ldg(0); sts(0); __syncthreads();
    for (int st = 0; st < 8; st++) {
        int b = st & 1;
        if (st < 7) ldg(st + 1);
#pragma unroll
        for (int ci = 0; ci < 8; ci++) {
            const float* f = &sA[b][ci][(col >> 2) * 32 + (col & 3) * 8];
            ulonglong2 A0 = *(const ulonglong2*)&f[0];    // (f0,f1),(f2,f3)
            ulonglong2 A1 = *(const ulonglong2*)&f[4];    // (f4,f5),(f6,f7)
            ull A2 = *(const ull*)&f[8];                  // (f8,f9)
            ull p1a = pairmid(A0.x, A0.y);                // (f1,f2)
            ull p1b = pairmid(A0.y, A1.x);                // (f3,f4)
            ull p1c = pairmid(A1.x, A1.y);                // (f5,f6)
            ull p1d = pairmid(A1.y, A2);                  // (f7,f8)
#pragma unroll
            for (int kw = 0; kw < 3; kw++) {
                ull P0 = kw == 0 ? A0.x : (kw == 1 ? p1a : A0.y);
                ull P1 = kw == 0 ? A0.y : (kw == 1 ? p1b : A1.x);
                ull P2 = kw == 0 ? A1.x : (kw == 1 ? p1c : A1.y);
                ull P3 = kw == 0 ? A1.y : (kw == 1 ? p1d : A2);
                const float* wrow = &sW[b][ci * 3 + kw][row * 8];
                float4 wa = *(const float4*)&wrow[0];
                float4 wb = *(const float4*)&wrow[4];
                float wf[8] = {wa.x, wa.y, wa.z, wa.w, wb.x, wb.y, wb.z, wb.w};
#pragma unroll
                for (int i = 0; i < 8; i++) {
                    ull wd = dup2(wf[i]);
                    if (ADDER) {
                        acc[i][0] = add2(acc[i][0], fma2(wd, NEG1X2, P0) & ABSM);
                        acc[i][1] = add2(acc[i][1], fma2(wd, NEG1X2, P1) & ABSM);
                        acc[i][2] = add2(acc[i][2], fma2(wd, NEG1X2, P2) & ABSM);
                        acc[i][3] = add2(acc[i][3], fma2(wd, NEG1X2, P3) & ABSM);
                    } else {
                        acc[i][0] = fma2(wd, P0, acc[i][0]);
                        acc[i][1] = fma2(wd, P1, acc[i][1]);
                        acc[i][2] = fma2(wd, P2, acc[i][2]);
                        acc[i][3] = fma2(wd, P3, acc[i][3]);
                    }
                }
            }
        }
        if (st < 7) sts(b ^ 1);
        __syncthreads();
    }
    // output: row rr = rp*2 + (col>>2), w0 = (col&3)*8, padded-32 layout
    const int qo = (rp * 2 + (col >> 2)) * 32 + (col & 3) * 8;
    float* __restrict__ out = ADDER ? g_p4[blockIdx.y] : g_p3[blockIdx.y];
#pragma unroll
    for (int i = 0; i < 8; i++) {
        int co = row * 8 + i;
#pragma unroll
        for (int j = 0; j < 4; j++)
            *(ull*)&out[co * NP32 + qo + 2 * j] = acc[i][j];
    }
}

// =========================================================================
// ky: y3 = sum of 6 conv partials (padded-32) -> padded 30x30 layout.
// =========================================================================
__global__ __launch_bounds__(128) void ky() {
    int e = blockIdx.x * 128 + threadIdx.x;     // 100352
    int chunk = e % 7;
    int rowid = e / 7;
    int h = rowid % 28;
    int n = (rowid / 28) & 3;
    int c = rowid / 112;
    int qo = c * NP32 + n * 896 + h * 32 + chunk * 4;
    float4 s = *(const float4*)&g_p3[0][qo];
#pragma unroll
    for (int t = 1; t < 6; t++) {
        float4 a = *(const float4*)&g_p3[t][qo];
        s.x += a.x; s.y += a.y; s.z += a.z; s.w += a.w;
    }
    int po = c * PADN + n * PIMG + (h + 1) * 30 + 1 + chunk * 4;
    g_y3p[po]     = s.x;
    g_y3p[po + 1] = s.y;
    g_y3p[po + 2] = s.z;
    g_y3p[po + 3] = s.w;
}

// Epilogue: out = relu( relu(bn2(-S)) + x ), S = sum of 6 adder partials.
__device__ __forceinline__ float epi1(float S, float xv, float scale, float shift) {
    float v = fmaxf(fmaf(-S, scale, shift), 0.f);
    return fmaxf(v + xv, 0.f);
}
__global__ __launch_bounds__(128) void kepi(const float* __restrict__ x,
                                             const float* __restrict__ g2,
                                             const float* __restrict__ b2,
                                             const float* __restrict__ m2,
                                             const float* __restrict__ v2,
                                             float* __restrict__ out) {
    int e = blockIdx.x * 128 + threadIdx.x;     // 100352
    int chunk = e % 7;
    int rowid = e / 7;
    int h = rowid % 28;
    int n = (rowid / 28) & 3;
    int c = rowid / 112;
    int qo = c * NP32 + n * 896 + h * 32 + chunk * 4;
    float scale = g2[c] / sqrtf(v2[c] + 1e-5f);
    float shift = b2[c] - m2[c] * scale;
    float4 s = *(const float4*)&g_p4[0][qo];
#pragma unroll
    for (int t = 1; t < 6; t++) {
        float4 a = *(const float4*)&g_p4[t][qo];
        s.x += a.x; s.y += a.y; s.z += a.z; s.w += a.w;
    }
    int xi = (n * CIN + c) * PP + h * 28 + chunk * 4;
    float4 xr = *(const float4*)&x[xi];
    float4 r;
    r.x = epi1(s.x, xr.x, scale, shift);
    r.y = epi1(s.y, xr.y, scale, shift);
    r.z = epi1(s.z, xr.z, scale, shift);
    r.w = epi1(s.w, xr.w, scale, shift);
    *(float4*)&out[xi] = r;
}

// =========================================================================
extern "C" void kernel_launch(void* const* d_in, const int* in_sizes, int n_in,
                              void* d_out, int out_size) {
    const float* x   = (const float*)d_in[0];
    const float* w1  = (const float*)d_in[1];
    const float* wa1 = (const float*)d_in[2];
    const float* g1  = (const float*)d_in[3];
    const float* b1  = (const float*)d_in[4];
    const float* m1  = (const float*)d_in[5];
    const float* v1  = (const float*)d_in[6];
    const float* w2  = (const float*)d_in[7];
    const float* wa2 = (const float*)d_in[8];
    const float* g2  = (const float*)d_in[9];
    const float* b2  = (const float*)d_in[10];
    const float* m2  = (const float*)d_in[11];
    const float* v2  = (const float*)d_in[12];
    float* out = (float*)d_out;

    kprep        <<<64,          256>>>(w1, wa1, w2, wa2, g1, b1, m1, v1);
    k1x1<false>  <<<98,          256>>>(x);
    k1x1<true>   <<<98,          256>>>(nullptr);
    k3x3<false>  <<<dim3(56, 6), 128>>>();
    ky           <<<784,         128>>>();
    k3x3<true>   <<<dim3(56, 6), 128>>>();
    kepi         <<<784,         128>>>(x, g2, b2, m2, v2, out);
}

// round 13
// speedup vs baseline: 1.4809x; 1.4809x over previous
#include <cuda_runtime.h>

#define CIN  128
#define PP   784          // 28*28
#define NPIX 3136         // 4*784
#define PIMG 900          // 30*30 padded image
#define PADN 3600         // 4*900 per channel
typedef unsigned long long ull;

// ---------------- scratch (device globals; no allocation) ----------------
__device__ __align__(16) float g_y1 [CIN * NPIX];     // conv1x1 out, [c][q]
__device__ __align__(16) float g_zp [CIN * PADN];     // z (bn1+relu), zero-padded 30x30
__device__ __align__(16) float g_p3 [6][CIN * NPIX];  // conv3x3 (kh,ciHalf) partials
__device__ __align__(16) float g_y3p[CIN * PADN];     // conv3x3 combined, zero-padded
__device__ __align__(16) float g_p4 [6][CIN * NPIX];  // adder3x3 partials (+S)
// transposed weights: [ci][co]
__device__ __align__(16) float g_w1t [CIN * CIN];
__device__ __align__(16) float g_wa1t[CIN * CIN];
__device__ __align__(16) float g_w2t [9][CIN * CIN];
__device__ __align__(16) float g_wa2t[9][CIN * CIN];
// BN1 folded params
__device__ float g_sc1[CIN], g_sh1[CIN];

// ---------------- packed f32x2 helpers -----------------------------------
__device__ __forceinline__ ull fma2(ull a, ull b, ull c) {
    ull d; asm("fma.rn.f32x2 %0, %1, %2, %3;" : "=l"(d) : "l"(a), "l"(b), "l"(c)); return d;
}
__device__ __forceinline__ ull add2(ull a, ull b) {
    ull d; asm("add.rn.f32x2 %0, %1, %2;" : "=l"(d) : "l"(a), "l"(b)); return d;
}
__device__ __forceinline__ ull dup2(float w) {
    ull d; asm("mov.b64 %0, {%1, %1};" : "=l"(d) : "f"(w)); return d;
}
__device__ __forceinline__ float lo32(ull v) { return __uint_as_float((unsigned)(v & 0xFFFFFFFFu)); }
__device__ __forceinline__ float hi32(ull v) { return __uint_as_float((unsigned)(v >> 32)); }
#define NEG1X2 0xBF800000BF800000ULL
#define ABSM   0x7FFFFFFF7FFFFFFFULL

// =========================================================================
// kprep: transpose weights; fold BN1.
// =========================================================================
__global__ __launch_bounds__(256) void kprep(const float* __restrict__ w1,
                                             const float* __restrict__ wa1,
                                             const float* __restrict__ w2,
                                             const float* __restrict__ wa2,
                                             const float* __restrict__ g1,
                                             const float* __restrict__ b1,
                                             const float* __restrict__ m1,
                                             const float* __restrict__ v1) {
    int i = blockIdx.x * 256 + threadIdx.x;     // 64 blocks -> 16384
    int ci = i >> 7, co = i & 127;
    g_w1t [ci * CIN + co] = w1 [co * CIN + ci];
    g_wa1t[ci * CIN + co] = wa1[co * CIN + ci];
#pragma unroll
    for (int t = 0; t < 9; t++) {
        g_w2t [t][ci * CIN + co] = w2 [(co * CIN + ci) * 9 + t];
        g_wa2t[t][ci * CIN + co] = wa2[(co * CIN + ci) * 9 + t];
    }
    if (blockIdx.x == 0 && threadIdx.x < CIN) {
        int c = threadIdx.x;
        float sc = g1[c] / sqrtf(v1[c] + 1e-5f);
        g_sc1[c] = sc;
        g_sh1[c] = b1[c] - m1[c] * sc;
    }
}

// =========================================================================
// k1/k2: 1x1 conv / adder, FULL ci. CTA 128co x 32px, 256 thr, tile 4co x 4px.
// grid (98). ADDER=true fuses BN1+ReLU, writes padded g_zp. (R11 winner)
// =========================================================================
template <bool ADDER>
__global__ __launch_bounds__(256) void k1x1(const float* __restrict__ x) {
    __shared__ __align__(16) float sA[2][16][32];
    __shared__ __align__(16) float sW[2][16][128];
    __shared__ int sT[32];

    const int tid = threadIdx.x;
    const int col = tid & 7, row = tid >> 3;
    const int qBase = blockIdx.x * 32;

    if (tid < 32) {
        int q = qBase + tid;
        int n = q / PP, p = q - n * PP;
        if (ADDER) {
            int h = p / 28, w = p - h * 28;
            sT[tid] = n * PIMG + (h + 1) * 30 + w + 1;
        } else {
            sT[tid] = n * CIN * PP + p;
        }
    }
    __syncthreads();

    ull acc[4][2];
#pragma unroll
    for (int i = 0; i < 4; i++) { acc[i][0] = 0; acc[i][1] = 0; }

    const float* __restrict__ wsrc = ADDER ? g_wa1t : g_w1t;

    float aReg[2];
    float4 wReg[2];
    auto ldg = [&](int s) {
        int ci0 = s << 4;
#pragma unroll
        for (int k = 0; k < 2; k++) {
            int e = k * 256 + tid;
            int ci = ci0 + (e >> 5), j = e & 31;
            if (ADDER) aReg[k] = g_y1[ci * NPIX + qBase + j];
            else       aReg[k] = x[sT[j] + ci * PP];
        }
#pragma unroll
        for (int k = 0; k < 2; k++) {
            int e4 = (k * 256 + tid) * 4;
            wReg[k] = *(const float4*)&wsrc[(ci0 + (e4 >> 7)) * CIN + (e4 & 127)];
        }
    };
    auto sts = [&](int b) {
#pragma unroll
        for (int k = 0; k < 2; k++) { int e = k * 256 + tid; sA[b][e >> 5][e & 31] = aReg[k]; }
#pragma unroll
        for (int k = 0; k < 2; k++) { int e4 = (k * 256 + tid) * 4; *(float4*)&sW[b][e4 >> 7][e4 & 127] = wReg[k]; }
    };

    ldg(0); sts(0); __syncthreads();
    for (int s = 0; s < 8; s++) {
        int b = s & 1;
        if (s < 7) ldg(s + 1);
#pragma unroll
        for (int ci = 0; ci < 16; ci++) {
            ulonglong2 a01 = *(const ulonglong2*)&sA[b][ci][col * 4];
            float4 w4 = *(const float4*)&sW[b][ci][row * 4];
            float wf[4] = {w4.x, w4.y, w4.z, w4.w};
#pragma unroll
            for (int i = 0; i < 4; i++) {
                ull wd = dup2(wf[i]);
                if (ADDER) {
                    acc[i][0] = add2(acc[i][0], fma2(wd, NEG1X2, a01.x) & ABSM);
                    acc[i][1] = add2(acc[i][1], fma2(wd, NEG1X2, a01.y) & ABSM);
                } else {
                    acc[i][0] = fma2(wd, a01.x, acc[i][0]);
                    acc[i][1] = fma2(wd, a01.y, acc[i][1]);
                }
            }
        }
        if (s < 7) sts(b ^ 1);
        __syncthreads();
    }
    if (ADDER) {
#pragma unroll
        for (int i = 0; i < 4; i++) {
            int co = row * 4 + i;
            float sc = g_sc1[co], sh = g_sh1[co];
            float r0 = fmaxf(fmaf(-lo32(acc[i][0]), sc, sh), 0.f);
            float r1 = fmaxf(fmaf(-hi32(acc[i][0]), sc, sh), 0.f);
            float r2 = fmaxf(fmaf(-lo32(acc[i][1]), sc, sh), 0.f);
            float r3 = fmaxf(fmaf(-hi32(acc[i][1]), sc, sh), 0.f);
            float* zc = &g_zp[co * PADN];
            zc[sT[col * 4]]     = r0;
            zc[sT[col * 4 + 1]] = r1;
            zc[sT[col * 4 + 2]] = r2;
            zc[sT[col * 4 + 3]] = r3;
        }
    } else {
        const int q = qBase + col * 4;
#pragma unroll
        for (int i = 0; i < 4; i++) {
            int co = row * 4 + i;
            *(ull*)&g_y1[co * NPIX + q]     = acc[i][0];
            *(ull*)&g_y1[co * NPIX + q + 2] = acc[i][1];
        }
    }
}

// =========================================================================
// k3/k4: 3x3 conv / adder. CTA 128co x (8*PXW)px, 128 thr, tile 8co x PXWpx.
// PXW=8 (conv, grid (49,6)): R9/R11 winner geometry, L1-co-saturated.
// PXW=4 (adder, grid (98,6)): half q-tile -> 588 CTAs -> 4 CTAs/SM, 16 warps
//   for the issue-bound packed-abs pipeline; L1 has headroom there.
// y = kh*2 + ciHalf. A staged branch-free from padded input.
// =========================================================================
template <bool ADDER, int PXW>
__global__ __launch_bounds__(128) void k3x3() {
    constexpr int QT = 8 * PXW;                  // CTA q-tile: 64 or 32
    constexpr int NA = QT / 8;                   // A staging regs per thread
    __shared__ __align__(16) float sA[2][16][QT];
    __shared__ __align__(16) float sW[2][16][128];
    __shared__ int sIdx[QT];

    const int tid = threadIdx.x;
    const int col = tid & 7, row = tid >> 3;
    const int qBase  = blockIdx.x * QT;
    const int kh     = blockIdx.y >> 1;
    const int ciBase = (blockIdx.y & 1) * 64;

    if (tid < QT) {
        int q = qBase + tid;
        int n = q / PP, p = q - n * PP;
        int h = p / 28, w = p - h * 28;
        sIdx[tid] = n * PIMG + (h + kh) * 30 + w;   // +kw at load; always valid
    }
    __syncthreads();

    ull acc[8][PXW / 2];
#pragma unroll
    for (int i = 0; i < 8; i++)
#pragma unroll
        for (int j = 0; j < PXW / 2; j++) acc[i][j] = 0;

    const float* __restrict__ in   = ADDER ? g_y3p : g_zp;
    const float* __restrict__ wsrc = ADDER ? &g_wa2t[0][0] : &g_w2t[0][0];

    float aReg[NA];
    float4 wReg[4];
    auto ldg = [&](int s) {
        int kw = s >> 2, ciOff = (s & 3) << 4;
        int cB = ciBase + ciOff;
#pragma unroll
        for (int k = 0; k < NA; k++) {              // A: 16ci x QTpx scalar
            int e = k * 128 + tid;
            aReg[k] = in[(cB + e / QT) * PADN + sIdx[e % QT] + kw];
        }
        const float* __restrict__ wslice = wsrc + (kh * 3 + kw) * (CIN * CIN);
#pragma unroll
        for (int k = 0; k < 4; k++) {               // W: 16ci x 128co float4
            int e4 = (k * 128 + tid) * 4;
            wReg[k] = *(const float4*)&wslice[(cB + (e4 >> 7)) * CIN + (e4 & 127)];
        }
    };
    auto sts = [&](int b) {
#pragma unroll
        for (int k = 0; k < NA; k++) { int e = k * 128 + tid; sA[b][e / QT][e % QT] = aReg[k]; }
#pragma unroll
        for (int k = 0; k < 4; k++) { int e4 = (k * 128 + tid) * 4; *(float4*)&sW[b][e4 >> 7][e4 & 127] = wReg[k]; }
    };

    ldg(0); sts(0); __syncthreads();
    for (int s = 0; s < 12; s++) {
        int b = s & 1;
        if (s < 11) ldg(s + 1);
#pragma unroll
        for (int ci = 0; ci < 16; ci++) {
            ull av[PXW / 2];
#pragma unroll
            for (int j = 0; j < PXW / 2; j += 2) {
                ulonglong2 t = *(const ulonglong2*)&sA[b][ci][col * PXW + j * 2];
                av[j] = t.x;
                if (j + 1 < PXW / 2) av[j + 1] = t.y;
            }
            float4 wa = *(const float4*)&sW[b][ci][row * 8];
            float4 wb = *(const float4*)&sW[b][ci][row * 8 + 4];
            float wf[8] = {wa.x, wa.y, wa.z, wa.w, wb.x, wb.y, wb.z, wb.w};
#pragma unroll
            for (int i = 0; i < 8; i++) {
                ull wd = dup2(wf[i]);
#pragma unroll
                for (int j = 0; j < PXW / 2; j++) {
                    if (ADDER) acc[i][j] = add2(acc[i][j], fma2(wd, NEG1X2, av[j]) & ABSM);
                    else       acc[i][j] = fma2(wd, av[j], acc[i][j]);
                }
            }
        }
        if (s < 11) sts(b ^ 1);
        __syncthreads();
    }
    const int q = qBase + col * PXW;
    float* __restrict__ out = ADDER ? g_p4[blockIdx.y] : g_p3[blockIdx.y];
#pragma unroll
    for (int i = 0; i < 8; i++) {
        int co = row * 8 + i;
#pragma unroll
        for (int j = 0; j < PXW / 2; j++)
            *(ull*)&out[co * NPIX + q + 2 * j] = acc[i][j];
    }
}

// =========================================================================
// ky: y3 = sum of 6 conv partials, written into padded layout.
// =========================================================================
__global__ __launch_bounds__(128) void ky() {
    int e = blockIdx.x * 128 + threadIdx.x;     // 100352
    int chunk = e % 7;
    int rowid = e / 7;
    int h = rowid % 28;
    int n = (rowid / 28) & 3;
    int c = rowid / 112;
    int qo = c * NPIX + n * PP + h * 28 + chunk * 4;
    float4 s = *(const float4*)&g_p3[0][qo];
#pragma unroll
    for (int t = 1; t < 6; t++) {
        float4 a = *(const float4*)&g_p3[t][qo];
        s.x += a.x; s.y += a.y; s.z += a.z; s.w += a.w;
    }
    int po = c * PADN + n * PIMG + (h + 1) * 30 + 1 + chunk * 4;
    g_y3p[po]     = s.x;
    g_y3p[po + 1] = s.y;
    g_y3p[po + 2] = s.z;
    g_y3p[po + 3] = s.w;
}

// Epilogue: out = relu( relu(bn2(-S)) + x ), S = sum of 6 adder partials.
__device__ __forceinline__ float epi1(float S, float xv, float scale, float shift) {
    float v = fmaxf(fmaf(-S, scale, shift), 0.f);
    return fmaxf(v + xv, 0.f);
}
__global__ __launch_bounds__(128) void kepi(const float* __restrict__ x,
                                             const float* __restrict__ g2,
                                             const float* __restrict__ b2,
                                             const float* __restrict__ m2,
                                             const float* __restrict__ v2,
                                             float* __restrict__ out) {
    int base = (blockIdx.x * 128 + threadIdx.x) * 4;
    int c = base / NPIX;
    int q = base - c * NPIX;
    int n = q / PP, p = q - n * PP;
    float scale = g2[c] / sqrtf(v2[c] + 1e-5f);
    float shift = b2[c] - m2[c] * scale;
    float4 s = *(const float4*)&g_p4[0][base];
#pragma unroll
    for (int t = 1; t < 6; t++) {
        float4 a = *(const float4*)&g_p4[t][base];
        s.x += a.x; s.y += a.y; s.z += a.z; s.w += a.w;
    }
    int xi = (n * CIN + c) * PP + p;
    float4 xr = *(const float4*)&x[xi];
    float4 r;
    r.x = epi1(s.x, xr.x, scale, shift);
    r.y = epi1(s.y, xr.y, scale, shift);
    r.z = epi1(s.z, xr.z, scale, shift);
    r.w = epi1(s.w, xr.w, scale, shift);
    *(float4*)&out[xi] = r;
}

// =========================================================================
extern "C" void kernel_launch(void* const* d_in, const int* in_sizes, int n_in,
                              void* d_out, int out_size) {
    const float* x   = (const float*)d_in[0];
    const float* w1  = (const float*)d_in[1];
    const float* wa1 = (const float*)d_in[2];
    const float* g1  = (const float*)d_in[3];
    const float* b1  = (const float*)d_in[4];
    const float* m1  = (const float*)d_in[5];
    const float* v1  = (const float*)d_in[6];
    const float* w2  = (const float*)d_in[7];
    const float* wa2 = (const float*)d_in[8];
    const float* g2  = (const float*)d_in[9];
    const float* b2  = (const float*)d_in[10];
    const float* m2  = (const float*)d_in[11];
    const float* v2  = (const float*)d_in[12];
    float* out = (float*)d_out;

    kprep           <<<64,          256>>>(w1, wa1, w2, wa2, g1, b1, m1, v1);
    k1x1<false>     <<<98,          256>>>(x);
    k1x1<true>      <<<98,          256>>>(nullptr);
    k3x3<false, 8>  <<<dim3(49, 6), 128>>>();
    ky              <<<784,         128>>>();
    k3x3<true, 4>   <<<dim3(98, 6), 128>>>();
    kepi            <<<784,         128>>>(x, g2, b2, m2, v2, out);
}